// round 1
// baseline (speedup 1.0000x reference)
#include <cuda_runtime.h>
#include <cstddef>

// Problem constants (fixed by the reference)
constexpr int BATCH = 128;
constexpr int CMAX  = 272;
constexpr int TLEN  = 512;
constexpr int D1    = 320;

// Tiling
constexpr int BM = 64;   // d-tile
constexpr int BN = 64;   // t-tile
constexpr int BK = 16;   // c-tile  (272 = 17 * 16, exact)

__global__ __launch_bounds__(256, 4)
void sbconv_kernel(const float* __restrict__ X,
                   const int*   __restrict__ sidx,
                   const float* __restrict__ W,
                   float*       __restrict__ out)
{
    const int b     = blockIdx.z;
    const int dTile = blockIdx.y * BM;
    const int tTile = blockIdx.x * BN;
    const int tid   = threadIdx.x;

    const int s = __ldg(&sidx[b]);
    const float* Wp = W + (size_t)s * D1 * CMAX;   // [D1, CMAX] row-major
    const float* Xp = X + (size_t)b * CMAX * TLEN; // [CMAX, T] row-major

    __shared__ float Ws[BK][BM];   // W tile transposed: Ws[k][m]
    __shared__ float Xs[BK][BN];   // X tile: Xs[k][n]

    const int ty = tid >> 4;       // 0..15 -> d micro-row group
    const int tx = tid & 15;       // 0..15 -> t micro-col group

    // Global-load mappings (one float4 each per k-step)
    const int wm = tid >> 2;             // 0..63  W row within tile
    const int wk = (tid & 3) * 4;        // 0,4,8,12 k offset
    const int xr = tid >> 4;             // 0..15  X row within k-tile
    const int xc = (tid & 15) * 4;       // 0..60  t offset

    float acc[4][4] = {};

    #pragma unroll 1
    for (int k0 = 0; k0 < CMAX; k0 += BK) {
        // Load W tile 64x16 (transposed into SMEM)
        float4 wv = *reinterpret_cast<const float4*>(
            Wp + (size_t)(dTile + wm) * CMAX + k0 + wk);
        Ws[wk + 0][wm] = wv.x;
        Ws[wk + 1][wm] = wv.y;
        Ws[wk + 2][wm] = wv.z;
        Ws[wk + 3][wm] = wv.w;

        // Load X tile 16x64 (coalesced float4)
        float4 xv = *reinterpret_cast<const float4*>(
            Xp + (size_t)(k0 + xr) * TLEN + tTile + xc);
        *reinterpret_cast<float4*>(&Xs[xr][xc]) = xv;

        __syncthreads();

        #pragma unroll
        for (int k = 0; k < BK; ++k) {
            float4 a = *reinterpret_cast<const float4*>(&Ws[k][ty * 4]);
            float4 x = *reinterpret_cast<const float4*>(&Xs[k][tx * 4]);
            float av[4] = {a.x, a.y, a.z, a.w};
            float xv4[4] = {x.x, x.y, x.z, x.w};
            #pragma unroll
            for (int i = 0; i < 4; ++i)
                #pragma unroll
                for (int j = 0; j < 4; ++j)
                    acc[i][j] = fmaf(av[i], xv4[j], acc[i][j]);
        }

        __syncthreads();
    }

    // Write 4x4 micro-tile as 4 float4 rows
    float* op = out + ((size_t)b * D1 + dTile + ty * 4) * TLEN + tTile + tx * 4;
    #pragma unroll
    for (int i = 0; i < 4; ++i) {
        float4 v = make_float4(acc[i][0], acc[i][1], acc[i][2], acc[i][3]);
        *reinterpret_cast<float4*>(op + (size_t)i * TLEN) = v;
    }
}

extern "C" void kernel_launch(void* const* d_in, const int* in_sizes, int n_in,
                              void* d_out, int out_size)
{
    const float* X    = (const float*)d_in[0];  // [B, CMAX, T]
    const int*   sidx = (const int*)  d_in[1];  // [B]
    const float* W    = (const float*)d_in[2];  // [NS, D1, CMAX]
    float*       out  = (float*)d_out;          // [B, D1, T]

    dim3 grid(TLEN / BN, D1 / BM, BATCH);  // (8, 5, 128)
    dim3 block(256);
    sbconv_kernel<<<grid, block>>>(X, sidx, W, out);
}

// round 2
// speedup vs baseline: 1.2801x; 1.2801x over previous
#include <cuda_runtime.h>
#include <cstddef>

// Problem constants
constexpr int BATCH = 128;
constexpr int CMAX  = 272;
constexpr int TLEN  = 512;
constexpr int D1    = 320;

// Tiling
constexpr int BM = 64;    // d-tile
constexpr int BN = 256;   // t-tile
constexpr int BK = 16;    // c-tile (272 = 17*16)
constexpr int WSTR  = 68; // padded stride of transposed W tile (kills 4-way store conflict, keeps 16B align)
constexpr int NTILE = CMAX / BK;  // 17

__device__ __forceinline__ void cp_async16(void* smem_dst, const void* gmem_src) {
    unsigned sm = (unsigned)__cvta_generic_to_shared(smem_dst);
    asm volatile("cp.async.cg.shared.global [%0], [%1], 16;\n" :: "r"(sm), "l"(gmem_src));
}
__device__ __forceinline__ void cp_commit() { asm volatile("cp.async.commit_group;\n"); }
template <int N>
__device__ __forceinline__ void cp_wait() { asm volatile("cp.async.wait_group %0;\n" :: "n"(N)); }

__global__ __launch_bounds__(256, 2)
void sbconv_kernel(const float* __restrict__ X,
                   const int*   __restrict__ sidx,
                   const float* __restrict__ W,
                   float*       __restrict__ out)
{
    __shared__ float Ws[2][BK * WSTR];   // W tile transposed: Ws[k][m], padded stride
    __shared__ float Xs[2][BK * BN];     // X tile: Xs[k][n]

    const int b     = blockIdx.z;
    const int dTile = blockIdx.y * BM;
    const int tTile = blockIdx.x * BN;
    const int tid   = threadIdx.x;

    const int s = __ldg(&sidx[b]);
    const float* Wp = W + ((size_t)s * D1 + dTile) * CMAX;
    const float* Xp = X + (size_t)b * CMAX * TLEN + tTile;

    // A (W) global-load mapping: one float4 per thread per tile
    const int wm = tid >> 2;         // 0..63  d-row within tile
    const int wk = (tid & 3) * 4;    // 0,4,8,12 c-offset
    const float* gA = Wp + (size_t)wm * CMAX + wk;

    // B (X) global-load mapping: four float4 per thread per tile (via cp.async)
    const int xr = tid >> 4;         // 0..15 c-row within tile
    const int xc = (tid & 15) * 4;   // 0..60 t-offset
    const float* gB = Xp + (size_t)xr * TLEN + xc;

    // Compute mapping: 8(d-groups) x 32(t-groups); 8x8 micro-tile each
    const int dg = tid >> 5;         // 0..7  (constant within a warp -> Ws reads broadcast)
    const int tg = tid & 31;         // 0..31

    float acc[8][8] = {};

    // ---- prologue: stage tile 0 ----
    {
        float4 wv = *reinterpret_cast<const float4*>(gA);
        Ws[0][(wk + 0) * WSTR + wm] = wv.x;
        Ws[0][(wk + 1) * WSTR + wm] = wv.y;
        Ws[0][(wk + 2) * WSTR + wm] = wv.z;
        Ws[0][(wk + 3) * WSTR + wm] = wv.w;
        #pragma unroll
        for (int j = 0; j < 4; ++j)
            cp_async16(&Xs[0][xr * BN + xc + 64 * j], gB + 64 * j);
        cp_commit();
    }
    cp_wait<0>();
    __syncthreads();

    int buf = 0;
    #pragma unroll 1
    for (int kt = 0; kt < NTILE; ++kt) {
        const bool more = (kt + 1 < NTILE);
        float4 wv;
        if (more) {
            // Prefetch next tile: W -> regs, X -> smem via cp.async
            wv = *reinterpret_cast<const float4*>(gA + (size_t)(kt + 1) * BK);
            #pragma unroll
            for (int j = 0; j < 4; ++j)
                cp_async16(&Xs[buf ^ 1][xr * BN + xc + 64 * j],
                           gB + (size_t)(kt + 1) * BK * TLEN + 64 * j);
            cp_commit();
        }

        // ---- compute on current buffer ----
        #pragma unroll
        for (int k = 0; k < BK; ++k) {
            float4 a0 = *reinterpret_cast<const float4*>(&Ws[buf][k * WSTR + dg * 8]);
            float4 a1 = *reinterpret_cast<const float4*>(&Ws[buf][k * WSTR + dg * 8 + 4]);
            float4 b0 = *reinterpret_cast<const float4*>(&Xs[buf][k * BN + tg * 8]);
            float4 b1 = *reinterpret_cast<const float4*>(&Xs[buf][k * BN + tg * 8 + 4]);
            float av[8] = {a0.x, a0.y, a0.z, a0.w, a1.x, a1.y, a1.z, a1.w};
            float bv[8] = {b0.x, b0.y, b0.z, b0.w, b1.x, b1.y, b1.z, b1.w};
            #pragma unroll
            for (int i = 0; i < 8; ++i)
                #pragma unroll
                for (int j = 0; j < 8; ++j)
                    acc[i][j] = fmaf(av[i], bv[j], acc[i][j]);
        }

        if (more) {
            Ws[buf ^ 1][(wk + 0) * WSTR + wm] = wv.x;
            Ws[buf ^ 1][(wk + 1) * WSTR + wm] = wv.y;
            Ws[buf ^ 1][(wk + 2) * WSTR + wm] = wv.z;
            Ws[buf ^ 1][(wk + 3) * WSTR + wm] = wv.w;
            cp_wait<0>();
            __syncthreads();
            buf ^= 1;
        }
    }

    // ---- epilogue: write 8x8 micro-tile ----
    float* op = out + ((size_t)b * D1 + dTile + dg * 8) * TLEN + tTile + tg * 8;
    #pragma unroll
    for (int i = 0; i < 8; ++i) {
        float4 v0 = make_float4(acc[i][0], acc[i][1], acc[i][2], acc[i][3]);
        float4 v1 = make_float4(acc[i][4], acc[i][5], acc[i][6], acc[i][7]);
        *reinterpret_cast<float4*>(op + (size_t)i * TLEN)     = v0;
        *reinterpret_cast<float4*>(op + (size_t)i * TLEN + 4) = v1;
    }
}

extern "C" void kernel_launch(void* const* d_in, const int* in_sizes, int n_in,
                              void* d_out, int out_size)
{
    const float* X    = (const float*)d_in[0];  // [B, CMAX, T]
    const int*   sidx = (const int*)  d_in[1];  // [B]
    const float* W    = (const float*)d_in[2];  // [NS, D1, CMAX]
    float*       out  = (float*)d_out;          // [B, D1, T]

    dim3 grid(TLEN / BN, D1 / BM, BATCH);  // (2, 5, 128)
    dim3 block(256);
    sbconv_kernel<<<grid, block>>>(X, sidx, W, out);
}

// round 4
// speedup vs baseline: 3.1412x; 2.4538x over previous
#include <cuda_runtime.h>
#include <cuda_fp16.h>
#include <mma.h>
#include <cstdint>
#include <cstddef>

using namespace nvcuda;

// Problem constants
constexpr int BATCH = 128;
constexpr int CMAX  = 272;
constexpr int TLEN  = 512;
constexpr int D1    = 320;

// Tiling
constexpr int BM = 64;    // d-tile
constexpr int BN = 128;   // t-tile
constexpr int BK = 32;    // c-chunk
constexpr int AST = BK + 8;   // A smem stride (halves) = 40
constexpr int BST = BN + 8;   // B smem stride (halves) = 136
constexpr int NIT = (CMAX + BK - 1) / BK;  // 9 (last chunk: 16 valid, zero-padded)

__global__ __launch_bounds__(256)
void sbconv_wmma_kernel(const float* __restrict__ X,
                        const int*   __restrict__ sidx,
                        const float* __restrict__ W,
                        float*       __restrict__ out)
{
    __shared__ __half As[BM * AST];   // W tile: [m][k], fp16
    __shared__ __half Bs[BK * BST];   // X tile: [k][n], fp16

    const int tid = threadIdx.x;
    const int b   = blockIdx.z;
    const int d0  = blockIdx.y * BM;
    const int t0  = blockIdx.x * BN;

    const int s = __ldg(&sidx[b]);
    const float* Wp = W + ((size_t)s * D1 + d0) * CMAX;  // [BM rows, CMAX]
    const float* Xp = X + (size_t)b * CMAX * TLEN + t0;  // [CMAX rows, TLEN]

    const int wid = tid >> 5;
    const int wm  = wid >> 2;   // 0..1  (d-direction)
    const int wn  = wid & 3;    // 0..3  (t-direction)

    wmma::fragment<wmma::accumulator, 16, 16, 16, float> acc[2][2];
    #pragma unroll
    for (int i = 0; i < 2; ++i)
        #pragma unroll
        for (int j = 0; j < 2; ++j)
            wmma::fill_fragment(acc[i][j], 0.0f);

    // Global-load mappings (float4 granularity)
    const int ar = tid >> 3;        // 0..31  A row (2 passes -> 64 rows)
    const int ak = (tid & 7) * 4;   // 0..28  A k-offset
    const int br = tid >> 5;        // 0..7   B k-row (4 passes -> 32 rows)
    const int bc = (tid & 31) * 4;  // 0..124 B t-offset

    #pragma unroll 1
    for (int it = 0; it < NIT; ++it) {
        const int k0 = it * BK;

        // ---- stage A (W) chunk: 64 x 32 fp32 -> fp16 ----
        #pragma unroll
        for (int p = 0; p < 2; ++p) {
            const int row = p * 32 + ar;
            float4 v = make_float4(0.f, 0.f, 0.f, 0.f);
            if (k0 + ak < CMAX)   // boundary 272 is float4-aligned
                v = *reinterpret_cast<const float4*>(Wp + (size_t)row * CMAX + k0 + ak);
            __half2 h0 = __floats2half2_rn(v.x, v.y);
            __half2 h1 = __floats2half2_rn(v.z, v.w);
            uint2 u;
            u.x = *reinterpret_cast<uint32_t*>(&h0);
            u.y = *reinterpret_cast<uint32_t*>(&h1);
            *reinterpret_cast<uint2*>(&As[row * AST + ak]) = u;
        }

        // ---- stage B (X) chunk: 32 x 128 fp32 -> fp16 ----
        #pragma unroll
        for (int p = 0; p < 4; ++p) {
            const int row = p * 8 + br;
            float4 v = make_float4(0.f, 0.f, 0.f, 0.f);
            if (k0 + row < CMAX)
                v = *reinterpret_cast<const float4*>(Xp + (size_t)(k0 + row) * TLEN + bc);
            __half2 h0 = __floats2half2_rn(v.x, v.y);
            __half2 h1 = __floats2half2_rn(v.z, v.w);
            uint2 u;
            u.x = *reinterpret_cast<uint32_t*>(&h0);
            u.y = *reinterpret_cast<uint32_t*>(&h1);
            *reinterpret_cast<uint2*>(&Bs[row * BST + bc]) = u;
        }

        __syncthreads();

        // ---- compute: 2 k-steps of 16 ----
        #pragma unroll
        for (int kk = 0; kk < BK; kk += 16) {
            wmma::fragment<wmma::matrix_a, 16, 16, 16, __half, wmma::row_major> af[2];
            wmma::fragment<wmma::matrix_b, 16, 16, 16, __half, wmma::row_major> bf[2];
            #pragma unroll
            for (int i = 0; i < 2; ++i)
                wmma::load_matrix_sync(af[i], &As[(wm * 32 + i * 16) * AST + kk], AST);
            #pragma unroll
            for (int j = 0; j < 2; ++j)
                wmma::load_matrix_sync(bf[j], &Bs[kk * BST + wn * 32 + j * 16], BST);
            #pragma unroll
            for (int i = 0; i < 2; ++i)
                #pragma unroll
                for (int j = 0; j < 2; ++j)
                    wmma::mma_sync(acc[i][j], af[i], bf[j], acc[i][j]);
        }

        __syncthreads();
    }

    // ---- epilogue: write 32x32 warp tile ----
    #pragma unroll
    for (int i = 0; i < 2; ++i)
        #pragma unroll
        for (int j = 0; j < 2; ++j) {
            float* op = out + ((size_t)b * D1 + d0 + wm * 32 + i * 16) * TLEN
                            + t0 + wn * 32 + j * 16;
            wmma::store_matrix_sync(op, acc[i][j], TLEN, wmma::mem_row_major);
        }
}

extern "C" void kernel_launch(void* const* d_in, const int* in_sizes, int n_in,
                              void* d_out, int out_size)
{
    const float* X    = (const float*)d_in[0];  // [B, CMAX, T]
    const int*   sidx = (const int*)  d_in[1];  // [B]
    const float* W    = (const float*)d_in[2];  // [NS, D1, CMAX]
    float*       out  = (float*)d_out;          // [B, D1, T]

    dim3 grid(TLEN / BN, D1 / BM, BATCH);  // (4, 5, 128)
    sbconv_wmma_kernel<<<grid, 256>>>(X, sidx, W, out);
}

// round 5
// speedup vs baseline: 3.7746x; 1.2016x over previous
#include <cuda_runtime.h>
#include <cuda_fp16.h>
#include <mma.h>
#include <cstdint>
#include <cstddef>

using namespace nvcuda;

// Problem constants
constexpr int BATCH = 128;
constexpr int CMAX  = 272;
constexpr int TLEN  = 512;
constexpr int D1    = 320;
constexpr int NSUBJ = 8;
constexpr int CPAD  = 288;   // 9 * 32, zero-padded channel dim

// fp16 scratch (conversion done once in a pre-pass)
__device__ __half Xh[(size_t)BATCH * CPAD * TLEN];  // 37.7 MB
__device__ __half Wh[(size_t)NSUBJ * D1 * CPAD];    // 1.5 MB

// ---------------- pre-convert kernel ----------------
constexpr int64_t NXV = (int64_t)BATCH * CPAD * TLEN / 8;  // 8-half vectors
constexpr int64_t NWV = (int64_t)NSUBJ * D1 * CPAD / 8;

__global__ __launch_bounds__(256)
void convert_kernel(const float* __restrict__ X, const float* __restrict__ W)
{
    const int64_t i = (int64_t)blockIdx.x * blockDim.x + threadIdx.x;
    if (i < NXV) {
        const int64_t h0 = i * 8;
        const int b   = (int)(h0 / ((int64_t)CPAD * TLEN));
        const int rem = (int)(h0 % ((int64_t)CPAD * TLEN));
        const int c   = rem / TLEN;
        const int t   = rem % TLEN;
        __half2 o[4] = {};
        if (c < CMAX) {
            const float4* src = reinterpret_cast<const float4*>(
                X + ((int64_t)b * CMAX + c) * TLEN + t);
            float4 v0 = src[0], v1 = src[1];
            o[0] = __floats2half2_rn(v0.x, v0.y);
            o[1] = __floats2half2_rn(v0.z, v0.w);
            o[2] = __floats2half2_rn(v1.x, v1.y);
            o[3] = __floats2half2_rn(v1.z, v1.w);
        }
        *reinterpret_cast<uint4*>(&Xh[h0]) = *reinterpret_cast<const uint4*>(o);
    } else if (i < NXV + NWV) {
        const int64_t h0 = (i - NXV) * 8;
        const int sd = (int)(h0 / CPAD);   // s*D1 + d
        const int c  = (int)(h0 % CPAD);   // multiple of 8; 272 % 8 == 0
        __half2 o[4] = {};
        if (c < CMAX) {
            const float4* src = reinterpret_cast<const float4*>(
                W + (int64_t)sd * CMAX + c);
            float4 v0 = src[0], v1 = src[1];
            o[0] = __floats2half2_rn(v0.x, v0.y);
            o[1] = __floats2half2_rn(v0.z, v0.w);
            o[2] = __floats2half2_rn(v1.x, v1.y);
            o[3] = __floats2half2_rn(v1.z, v1.w);
        }
        *reinterpret_cast<uint4*>(&Wh[h0]) = *reinterpret_cast<const uint4*>(o);
    }
}

// ---------------- GEMM kernel ----------------
constexpr int BM = 64;
constexpr int BN = 256;
constexpr int BK = 32;
constexpr int STAGES = 3;
constexpr int NIT = CPAD / BK;   // 9, no predicates
constexpr int AST = BK + 8;      // 40 halves
constexpr int BST = BN + 8;      // 264 halves
constexpr int A_HALVES = BM * AST;   // 2560
constexpr int B_HALVES = BK * BST;   // 8448
constexpr int STAGE_HALVES = A_HALVES + B_HALVES;        // 11008
constexpr int SMEM_BYTES = STAGES * STAGE_HALVES * 2;    // 66048

__device__ __forceinline__ void cp_async16(void* smem_dst, const void* gmem_src) {
    unsigned sm = (unsigned)__cvta_generic_to_shared(smem_dst);
    asm volatile("cp.async.ca.shared.global [%0], [%1], 16;\n" :: "r"(sm), "l"(gmem_src));
}
__device__ __forceinline__ void cp_commit() { asm volatile("cp.async.commit_group;\n"); }
template <int N>
__device__ __forceinline__ void cp_wait() { asm volatile("cp.async.wait_group %0;\n" :: "n"(N)); }

__global__ __launch_bounds__(256, 2)
void sbconv_wmma_kernel(const int* __restrict__ sidx, float* __restrict__ out)
{
    extern __shared__ __half smem[];

    const int tid = threadIdx.x;
    const int b   = blockIdx.z;
    const int d0  = blockIdx.y * BM;
    const int t0  = blockIdx.x * BN;

    const int s = __ldg(&sidx[b]);
    const __half* Wp = Wh + ((size_t)s * D1 + d0) * CPAD;  // [BM, CPAD]
    const __half* Xp = Xh + (size_t)b * CPAD * TLEN + t0;  // [CPAD, TLEN]

    const int wid = tid >> 5;
    const int wm  = wid >> 2;   // 0..1  d-direction (32 rows each)
    const int wn  = wid & 3;    // 0..3  t-direction (64 cols each)

    // cp.async mappings
    const int a_row = tid >> 2;          // 0..63
    const int a_col = (tid & 3) * 8;     // halves: 0,8,16,24 (1 x 16B each)
    const int b_row = tid >> 3;          // 0..31
    const int b_col = (tid & 7) * 32;    // halves: 4 x 16B contiguous

    auto stageA = [&](int it, int slot) {
        __half* As = smem + slot * STAGE_HALVES;
        const __half* src = Wp + (size_t)a_row * CPAD + it * BK + a_col;
        cp_async16(&As[a_row * AST + a_col], src);
    };
    auto stageB = [&](int it, int slot) {
        __half* Bs = smem + slot * STAGE_HALVES + A_HALVES;
        const __half* src = Xp + (size_t)(it * BK + b_row) * TLEN + b_col;
        #pragma unroll
        for (int j = 0; j < 4; ++j)
            cp_async16(&Bs[b_row * BST + b_col + j * 8], src + j * 8);
    };

    wmma::fragment<wmma::accumulator, 16, 16, 16, float> acc[2][4];
    #pragma unroll
    for (int i = 0; i < 2; ++i)
        #pragma unroll
        for (int j = 0; j < 4; ++j)
            wmma::fill_fragment(acc[i][j], 0.0f);

    // Prologue: stage 0 and 1
    #pragma unroll
    for (int st = 0; st < STAGES - 1; ++st) {
        stageA(st, st);
        stageB(st, st);
        cp_commit();
    }

    #pragma unroll 1
    for (int it = 0; it < NIT; ++it) {
        cp_wait<STAGES - 2>();
        __syncthreads();

        // Prefetch stage it+2 into the slot freed by compute(it-1)
        if (it + STAGES - 1 < NIT) {
            const int nslot = (it + STAGES - 1) % STAGES;
            stageA(it + STAGES - 1, nslot);
            stageB(it + STAGES - 1, nslot);
        }
        cp_commit();   // always commit (empty groups keep the count uniform)

        const int slot = it % STAGES;
        const __half* As = smem + slot * STAGE_HALVES;
        const __half* Bs = As + A_HALVES;

        #pragma unroll
        for (int kk = 0; kk < BK; kk += 16) {
            wmma::fragment<wmma::matrix_a, 16, 16, 16, __half, wmma::row_major> af[2];
            wmma::fragment<wmma::matrix_b, 16, 16, 16, __half, wmma::row_major> bf[4];
            #pragma unroll
            for (int i = 0; i < 2; ++i)
                wmma::load_matrix_sync(af[i], &As[(wm * 32 + i * 16) * AST + kk], AST);
            #pragma unroll
            for (int j = 0; j < 4; ++j)
                wmma::load_matrix_sync(bf[j], &Bs[kk * BST + wn * 64 + j * 16], BST);
            #pragma unroll
            for (int i = 0; i < 2; ++i)
                #pragma unroll
                for (int j = 0; j < 4; ++j)
                    wmma::mma_sync(acc[i][j], af[i], bf[j], acc[i][j]);
        }
        __syncthreads();
    }

    // Epilogue: warp writes its 32x64 tile
    #pragma unroll
    for (int i = 0; i < 2; ++i)
        #pragma unroll
        for (int j = 0; j < 4; ++j) {
            float* op = out + ((size_t)b * D1 + d0 + wm * 32 + i * 16) * TLEN
                            + t0 + wn * 64 + j * 16;
            wmma::store_matrix_sync(op, acc[i][j], TLEN, wmma::mem_row_major);
        }
}

extern "C" void kernel_launch(void* const* d_in, const int* in_sizes, int n_in,
                              void* d_out, int out_size)
{
    const float* X    = (const float*)d_in[0];  // [B, CMAX, T]
    const int*   sidx = (const int*)  d_in[1];  // [B]
    const float* W    = (const float*)d_in[2];  // [NS, D1, CMAX]
    float*       out  = (float*)d_out;          // [B, D1, T]

    // Pass 1: fp32 -> fp16 conversion (X once, W once)
    const int64_t total = NXV + NWV;
    const int cblocks = (int)((total + 255) / 256);
    convert_kernel<<<cblocks, 256>>>(X, W);

    // Pass 2: fp16 tensor-core GEMM
    static bool attr_set = false;
    if (!attr_set) {
        cudaFuncSetAttribute(sbconv_wmma_kernel,
                             cudaFuncAttributeMaxDynamicSharedMemorySize, SMEM_BYTES);
        attr_set = true;
    }
    dim3 grid(TLEN / BN, D1 / BM, BATCH);  // (2, 5, 128)
    sbconv_wmma_kernel<<<grid, 256, SMEM_BYTES>>>(sidx, out);
}